// round 15
// baseline (speedup 1.0000x reference)
#include <cuda_runtime.h>
#include <cuda_fp16.h>
#include <math.h>
#include <stdint.h>

#define NN 20000
#define EE 320000
#define DD 256
#define HH 8
#define LL 2
#define HUSZ 1024
#define QKVW 768

// ---------------- scratch (no allocation allowed) ----------------
__device__ __half g_h16[NN * DD];
__device__ __half g_qkv16[NN * QKVW];
__device__ __half g_agg16[NN * DD];
__device__ __half g_ffn16[NN * HUSZ];
__device__ __half g_wqkvT[LL * QKVW * DD];
__device__ __half g_woT[LL * DD * DD];
__device__ __half g_w1T[HUSZ * DD];
__device__ __half g_w2T[DD * HUSZ];
__device__ int    g_cnt[NN];
__device__ int    g_off[NN + 1];
__device__ int    g_cur[NN];
__device__ int    g_csrc[EE];

// ---------------- helpers ----------------
__device__ __forceinline__ void cp16h(__half* smem_ptr, const __half* gptr, bool p) {
    unsigned s = (unsigned)__cvta_generic_to_shared(smem_ptr);
    int bytes = p ? 16 : 0;
    asm volatile("cp.async.cg.shared.global [%0], [%1], 16, %2;\n"
                 :: "r"(s), "l"(gptr), "r"(bytes));
}
__device__ __forceinline__ void cp_commit() { asm volatile("cp.async.commit_group;\n" ::: "memory"); }
template <int N>
__device__ __forceinline__ void cp_wait() { asm volatile("cp.async.wait_group %0;\n" :: "n"(N) : "memory"); }

#define HSTRIDE 40
#define NSTAGE 3

// ================ gemm_h: BM=128, BN=128 ================
#define H_STAGE (128 * HSTRIDE)
#define GEMM_SMEM ((size_t)NSTAGE * 2 * H_STAGE * sizeof(__half))

__global__ __launch_bounds__(256) void gemm_h(
    const __half* __restrict__ A, const __half* __restrict__ BT,
    const float* __restrict__ bias, float* __restrict__ Cf, __half* __restrict__ Ch,
    int M, int Nc, int Kc, int relu)
{
    extern __shared__ __half smh[];

    const int tid = threadIdx.x;
    const int wid = tid >> 5;
    const int lane = tid & 31;
    const int g = lane >> 2;
    const int t = lane & 3;

    const int warp_m = wid >> 2;
    const int warp_n = wid & 3;
    const int row0 = blockIdx.y * 128;
    const int col0 = blockIdx.x * 128;

    const uint32_t sh0 = (uint32_t)__cvta_generic_to_shared(smh);

    const int a_lane = ((lane & 7) + ((lane >> 3) & 1) * 8) * HSTRIDE + (lane >> 4) * 8;
    const int b_lane4 = (lane & 7) * HSTRIDE + ((lane >> 3) & 1) * 8 + (lane >> 4) * 8 * HSTRIDE;

    float acc[4][4][4];
    #pragma unroll
    for (int mi = 0; mi < 4; mi++)
        #pragma unroll
        for (int ni = 0; ni < 4; ni++)
            #pragma unroll
            for (int r = 0; r < 4; r++) acc[mi][ni][r] = 0.f;

    const int ntiles = Kc >> 5;

    auto load_stage = [&](int st, int k0) {
        __half* as = smh + st * H_STAGE;
        __half* bs = smh + (NSTAGE + st) * H_STAGE;
        #pragma unroll
        for (int i = 0; i < 2; i++) {
            int lin = i * 256 + tid;
            int row = lin >> 2;
            int seg = (lin & 3) * 8;
            cp16h(&as[row * HSTRIDE + seg],
                  &A[(size_t)(row0 + row) * Kc + k0 + seg],
                  row0 + row < M);
            cp16h(&bs[row * HSTRIDE + seg],
                  &BT[(size_t)(col0 + row) * Kc + k0 + seg],
                  true);
        }
    };

    load_stage(0, 0);
    cp_commit();
    load_stage(1, 32);
    cp_commit();

    for (int kt = 0; kt < ntiles; kt++) {
        cp_wait<1>();
        __syncthreads();
        if (kt + 2 < ntiles) load_stage((kt + 2) % NSTAGE, (kt + 2) * 32);
        cp_commit();

        const int st = kt % NSTAGE;
        const uint32_t as_b = sh0 + (uint32_t)(st * H_STAGE) * 2;
        const uint32_t bs_b = sh0 + (uint32_t)((NSTAGE + st) * H_STAGE) * 2;

        #pragma unroll
        for (int ks = 0; ks < 2; ks++) {
            const int kk = ks * 16;
            const uint32_t a_base = as_b + 2u * (warp_m * 64 * HSTRIDE + kk + a_lane);
            const uint32_t b_base = bs_b + 2u * (warp_n * 32 * HSTRIDE + kk + b_lane4);

            unsigned af[4][4];
            #pragma unroll
            for (int mi = 0; mi < 4; mi++) {
                uint32_t addr = a_base + 2u * (mi * 16 * HSTRIDE);
                asm volatile("ldmatrix.sync.aligned.m8n8.x4.shared.b16 {%0,%1,%2,%3}, [%4];"
                             : "=r"(af[mi][0]), "=r"(af[mi][1]), "=r"(af[mi][2]), "=r"(af[mi][3])
                             : "r"(addr));
            }
            unsigned bf[4][2];
            #pragma unroll
            for (int np = 0; np < 2; np++) {
                uint32_t addr = b_base + 2u * (np * 16 * HSTRIDE);
                asm volatile("ldmatrix.sync.aligned.m8n8.x4.shared.b16 {%0,%1,%2,%3}, [%4];"
                             : "=r"(bf[2 * np][0]), "=r"(bf[2 * np][1]),
                               "=r"(bf[2 * np + 1][0]), "=r"(bf[2 * np + 1][1])
                             : "r"(addr));
            }
            #pragma unroll
            for (int mi = 0; mi < 4; mi++)
                #pragma unroll
                for (int ni = 0; ni < 4; ni++) {
                    asm volatile(
                        "mma.sync.aligned.m16n8k16.row.col.f32.f16.f16.f32 "
                        "{%0,%1,%2,%3}, {%4,%5,%6,%7}, {%8,%9}, {%0,%1,%2,%3};"
                        : "+f"(acc[mi][ni][0]), "+f"(acc[mi][ni][1]),
                          "+f"(acc[mi][ni][2]), "+f"(acc[mi][ni][3])
                        : "r"(af[mi][0]), "r"(af[mi][1]), "r"(af[mi][2]), "r"(af[mi][3]),
                          "r"(bf[ni][0]), "r"(bf[ni][1]));
                }
        }
    }

    #pragma unroll
    for (int mi = 0; mi < 4; mi++) {
        int rb = row0 + warp_m * 64 + mi * 16 + g;
        #pragma unroll
        for (int ni = 0; ni < 4; ni++) {
            int cb = col0 + warp_n * 32 + ni * 8 + 2 * t;
            #pragma unroll
            for (int half = 0; half < 2; half++) {
                int r = rb + half * 8;
                if (r >= M) continue;
                float v0 = acc[mi][ni][half * 2 + 0];
                float v1 = acc[mi][ni][half * 2 + 1];
                if (bias) { v0 += bias[cb]; v1 += bias[cb + 1]; }
                if (relu) { v0 = fmaxf(v0, 0.f); v1 = fmaxf(v1, 0.f); }
                if (Ch) {
                    *reinterpret_cast<__half2*>(&Ch[(size_t)r * Nc + cb]) =
                        __floats2half2_rn(v0, v1);
                } else {
                    *reinterpret_cast<float2*>(&Cf[(size_t)r * Nc + cb]) =
                        make_float2(v0, v1);
                }
            }
        }
    }
}

// ================ gemm_h64: BM=64, BN=128 ================
#define A64_STAGE (64 * HSTRIDE)
#define B64_STAGE (128 * HSTRIDE)
#define GEMM64_SMEM ((size_t)NSTAGE * (A64_STAGE + B64_STAGE) * sizeof(__half))

__global__ __launch_bounds__(256) void gemm_h64(
    const __half* __restrict__ A, const __half* __restrict__ BT,
    const float* __restrict__ bias, float* __restrict__ Cf, __half* __restrict__ Ch,
    int M, int Nc, int Kc, int relu)
{
    extern __shared__ __half smh[];

    const int tid = threadIdx.x;
    const int wid = tid >> 5;
    const int lane = tid & 31;
    const int g = lane >> 2;
    const int t = lane & 3;

    const int warp_m = wid >> 2;
    const int warp_n = wid & 3;
    const int row0 = blockIdx.y * 64;
    const int col0 = blockIdx.x * 128;

    const uint32_t sh0 = (uint32_t)__cvta_generic_to_shared(smh);

    const int a_lane = ((lane & 7) + ((lane >> 3) & 1) * 8) * HSTRIDE + (lane >> 4) * 8;
    const int b_lane4 = (lane & 7) * HSTRIDE + ((lane >> 3) & 1) * 8 + (lane >> 4) * 8 * HSTRIDE;

    float acc[2][4][4];
    #pragma unroll
    for (int mi = 0; mi < 2; mi++)
        #pragma unroll
        for (int ni = 0; ni < 4; ni++)
            #pragma unroll
            for (int r = 0; r < 4; r++) acc[mi][ni][r] = 0.f;

    const int ntiles = Kc >> 5;

    auto load_stage = [&](int st, int k0) {
        __half* as = smh + st * A64_STAGE;
        __half* bs = smh + NSTAGE * A64_STAGE + st * B64_STAGE;
        {
            int row = tid >> 2;
            int seg = (tid & 3) * 8;
            cp16h(&as[row * HSTRIDE + seg],
                  &A[(size_t)(row0 + row) * Kc + k0 + seg],
                  row0 + row < M);
        }
        #pragma unroll
        for (int i = 0; i < 2; i++) {
            int lin = i * 256 + tid;
            int row = lin >> 2;
            int seg = (lin & 3) * 8;
            cp16h(&bs[row * HSTRIDE + seg],
                  &BT[(size_t)(col0 + row) * Kc + k0 + seg],
                  true);
        }
    };

    load_stage(0, 0);
    cp_commit();
    load_stage(1, 32);
    cp_commit();

    for (int kt = 0; kt < ntiles; kt++) {
        cp_wait<1>();
        __syncthreads();
        if (kt + 2 < ntiles) load_stage((kt + 2) % NSTAGE, (kt + 2) * 32);
        cp_commit();

        const int st = kt % NSTAGE;
        const uint32_t as_b = sh0 + (uint32_t)(st * A64_STAGE) * 2;
        const uint32_t bs_b = sh0 + (uint32_t)(NSTAGE * A64_STAGE + st * B64_STAGE) * 2;

        #pragma unroll
        for (int ks = 0; ks < 2; ks++) {
            const int kk = ks * 16;
            const uint32_t a_base = as_b + 2u * (warp_m * 32 * HSTRIDE + kk + a_lane);
            const uint32_t b_base = bs_b + 2u * (warp_n * 32 * HSTRIDE + kk + b_lane4);

            unsigned af[2][4];
            #pragma unroll
            for (int mi = 0; mi < 2; mi++) {
                uint32_t addr = a_base + 2u * (mi * 16 * HSTRIDE);
                asm volatile("ldmatrix.sync.aligned.m8n8.x4.shared.b16 {%0,%1,%2,%3}, [%4];"
                             : "=r"(af[mi][0]), "=r"(af[mi][1]), "=r"(af[mi][2]), "=r"(af[mi][3])
                             : "r"(addr));
            }
            unsigned bf[4][2];
            #pragma unroll
            for (int np = 0; np < 2; np++) {
                uint32_t addr = b_base + 2u * (np * 16 * HSTRIDE);
                asm volatile("ldmatrix.sync.aligned.m8n8.x4.shared.b16 {%0,%1,%2,%3}, [%4];"
                             : "=r"(bf[2 * np][0]), "=r"(bf[2 * np][1]),
                               "=r"(bf[2 * np + 1][0]), "=r"(bf[2 * np + 1][1])
                             : "r"(addr));
            }
            #pragma unroll
            for (int mi = 0; mi < 2; mi++)
                #pragma unroll
                for (int ni = 0; ni < 4; ni++) {
                    asm volatile(
                        "mma.sync.aligned.m16n8k16.row.col.f32.f16.f16.f32 "
                        "{%0,%1,%2,%3}, {%4,%5,%6,%7}, {%8,%9}, {%0,%1,%2,%3};"
                        : "+f"(acc[mi][ni][0]), "+f"(acc[mi][ni][1]),
                          "+f"(acc[mi][ni][2]), "+f"(acc[mi][ni][3])
                        : "r"(af[mi][0]), "r"(af[mi][1]), "r"(af[mi][2]), "r"(af[mi][3]),
                          "r"(bf[ni][0]), "r"(bf[ni][1]));
                }
        }
    }

    #pragma unroll
    for (int mi = 0; mi < 2; mi++) {
        int rb = row0 + warp_m * 32 + mi * 16 + g;
        #pragma unroll
        for (int ni = 0; ni < 4; ni++) {
            int cb = col0 + warp_n * 32 + ni * 8 + 2 * t;
            #pragma unroll
            for (int half = 0; half < 2; half++) {
                int r = rb + half * 8;
                if (r >= M) continue;
                float v0 = acc[mi][ni][half * 2 + 0];
                float v1 = acc[mi][ni][half * 2 + 1];
                if (bias) { v0 += bias[cb]; v1 += bias[cb + 1]; }
                if (relu) { v0 = fmaxf(v0, 0.f); v1 = fmaxf(v1, 0.f); }
                if (Ch) {
                    *reinterpret_cast<__half2*>(&Ch[(size_t)r * Nc + cb]) =
                        __floats2half2_rn(v0, v1);
                } else {
                    *reinterpret_cast<float2*>(&Cf[(size_t)r * Nc + cb]) =
                        make_float2(v0, v1);
                }
            }
        }
    }
}

// ================ gemm_ln: BM=32, BN=256 Wo GEMM + residual + LayerNorm =====
// h = LayerNorm(agg @ Wo^T + h) * gamma + beta, h fp16 in/out.
#define ALN_STAGE (32 * HSTRIDE)
#define BLN_STAGE (256 * HSTRIDE)
#define GEMMLN_SMEM ((size_t)NSTAGE * (ALN_STAGE + BLN_STAGE) * sizeof(__half))

__global__ __launch_bounds__(256) void gemm_ln(
    const __half* __restrict__ A, const __half* __restrict__ BT,
    __half* __restrict__ h,
    const float* __restrict__ gamma, const float* __restrict__ beta)
{
    extern __shared__ __half smh[];
    __shared__ float red_s[32][4];
    __shared__ float red_q[32][4];

    const int tid = threadIdx.x;
    const int wid = tid >> 5;
    const int lane = tid & 31;
    const int g = lane >> 2;
    const int t = lane & 3;

    const int warp_m = wid >> 2;     // 0..1, 16 rows each
    const int warp_n = wid & 3;      // 0..3, 64 cols each
    const int row0 = blockIdx.x * 32;

    const uint32_t sh0 = (uint32_t)__cvta_generic_to_shared(smh);

    const int a_lane = ((lane & 7) + ((lane >> 3) & 1) * 8) * HSTRIDE + (lane >> 4) * 8;
    const int b_lane4 = (lane & 7) * HSTRIDE + ((lane >> 3) & 1) * 8 + (lane >> 4) * 8 * HSTRIDE;

    float acc[8][4];
    #pragma unroll
    for (int ni = 0; ni < 8; ni++)
        #pragma unroll
        for (int r = 0; r < 4; r++) acc[ni][r] = 0.f;

    auto load_stage = [&](int st, int k0) {
        __half* as = smh + st * ALN_STAGE;
        __half* bs = smh + NSTAGE * ALN_STAGE + st * BLN_STAGE;
        if (tid < 128) {
            int row = tid >> 2;
            int seg = (tid & 3) * 8;
            cp16h(&as[row * HSTRIDE + seg],
                  &A[(size_t)(row0 + row) * DD + k0 + seg], true);
        }
        #pragma unroll
        for (int i = 0; i < 4; i++) {
            int lin = i * 256 + tid;
            int row = lin >> 2;
            int seg = (lin & 3) * 8;
            cp16h(&bs[row * HSTRIDE + seg],
                  &BT[(size_t)row * DD + k0 + seg], true);
        }
    };

    load_stage(0, 0);
    cp_commit();
    load_stage(1, 32);
    cp_commit();

    const int ntiles = DD >> 5;   // 8
    for (int kt = 0; kt < ntiles; kt++) {
        cp_wait<1>();
        __syncthreads();
        if (kt + 2 < ntiles) load_stage((kt + 2) % NSTAGE, (kt + 2) * 32);
        cp_commit();

        const int st = kt % NSTAGE;
        const uint32_t as_b = sh0 + (uint32_t)(st * ALN_STAGE) * 2;
        const uint32_t bs_b = sh0 + (uint32_t)(NSTAGE * ALN_STAGE + st * BLN_STAGE) * 2;

        #pragma unroll
        for (int ks = 0; ks < 2; ks++) {
            const int kk = ks * 16;
            const uint32_t a_base = as_b + 2u * (warp_m * 16 * HSTRIDE + kk + a_lane);
            const uint32_t b_base = bs_b + 2u * (warp_n * 64 * HSTRIDE + kk + b_lane4);

            unsigned af[4];
            asm volatile("ldmatrix.sync.aligned.m8n8.x4.shared.b16 {%0,%1,%2,%3}, [%4];"
                         : "=r"(af[0]), "=r"(af[1]), "=r"(af[2]), "=r"(af[3])
                         : "r"(a_base));
            unsigned bf[8][2];
            #pragma unroll
            for (int np = 0; np < 4; np++) {
                uint32_t addr = b_base + 2u * (np * 16 * HSTRIDE);
                asm volatile("ldmatrix.sync.aligned.m8n8.x4.shared.b16 {%0,%1,%2,%3}, [%4];"
                             : "=r"(bf[2 * np][0]), "=r"(bf[2 * np][1]),
                               "=r"(bf[2 * np + 1][0]), "=r"(bf[2 * np + 1][1])
                             : "r"(addr));
            }
            #pragma unroll
            for (int ni = 0; ni < 8; ni++) {
                asm volatile(
                    "mma.sync.aligned.m16n8k16.row.col.f32.f16.f16.f32 "
                    "{%0,%1,%2,%3}, {%4,%5,%6,%7}, {%8,%9}, {%0,%1,%2,%3};"
                    : "+f"(acc[ni][0]), "+f"(acc[ni][1]),
                      "+f"(acc[ni][2]), "+f"(acc[ni][3])
                    : "r"(af[0]), "r"(af[1]), "r"(af[2]), "r"(af[3]),
                      "r"(bf[ni][0]), "r"(bf[ni][1]));
            }
        }
    }

    // ---- fused residual + LayerNorm epilogue ----
    const int r0 = row0 + warp_m * 16 + g;
    const int r1 = r0 + 8;

    float s0 = 0.f, q0 = 0.f, s1 = 0.f, q1 = 0.f;
    #pragma unroll
    for (int ni = 0; ni < 8; ni++) {
        int cb = warp_n * 64 + ni * 8 + 2 * t;
        float2 f0 = __half22float2(*reinterpret_cast<const __half2*>(&h[(size_t)r0 * DD + cb]));
        float2 f1 = __half22float2(*reinterpret_cast<const __half2*>(&h[(size_t)r1 * DD + cb]));
        float xa = acc[ni][0] + f0.x, xb = acc[ni][1] + f0.y;
        float xc = acc[ni][2] + f1.x, xd = acc[ni][3] + f1.y;
        s0 += xa + xb; q0 += xa * xa + xb * xb;
        s1 += xc + xd; q1 += xc * xc + xd * xd;
    }
    s0 += __shfl_xor_sync(0xffffffffu, s0, 1);
    q0 += __shfl_xor_sync(0xffffffffu, q0, 1);
    s1 += __shfl_xor_sync(0xffffffffu, s1, 1);
    q1 += __shfl_xor_sync(0xffffffffu, q1, 1);
    s0 += __shfl_xor_sync(0xffffffffu, s0, 2);
    q0 += __shfl_xor_sync(0xffffffffu, q0, 2);
    s1 += __shfl_xor_sync(0xffffffffu, s1, 2);
    q1 += __shfl_xor_sync(0xffffffffu, q1, 2);
    if (t == 0) {
        red_s[warp_m * 16 + g][warp_n] = s0;
        red_q[warp_m * 16 + g][warp_n] = q0;
        red_s[warp_m * 16 + g + 8][warp_n] = s1;
        red_q[warp_m * 16 + g + 8][warp_n] = q1;
    }
    __syncthreads();
    float S0 = red_s[warp_m * 16 + g][0] + red_s[warp_m * 16 + g][1]
             + red_s[warp_m * 16 + g][2] + red_s[warp_m * 16 + g][3];
    float Q0 = red_q[warp_m * 16 + g][0] + red_q[warp_m * 16 + g][1]
             + red_q[warp_m * 16 + g][2] + red_q[warp_m * 16 + g][3];
    float S1 = red_s[warp_m * 16 + g + 8][0] + red_s[warp_m * 16 + g + 8][1]
             + red_s[warp_m * 16 + g + 8][2] + red_s[warp_m * 16 + g + 8][3];
    float Q1 = red_q[warp_m * 16 + g + 8][0] + red_q[warp_m * 16 + g + 8][1]
             + red_q[warp_m * 16 + g + 8][2] + red_q[warp_m * 16 + g + 8][3];

    float mu0 = S0 * (1.f / DD);
    float inv0 = rsqrtf(fmaxf(Q0 * (1.f / DD) - mu0 * mu0, 0.f) + 1e-5f);
    float mu1 = S1 * (1.f / DD);
    float inv1 = rsqrtf(fmaxf(Q1 * (1.f / DD) - mu1 * mu1, 0.f) + 1e-5f);

    #pragma unroll
    for (int ni = 0; ni < 8; ni++) {
        int cb = warp_n * 64 + ni * 8 + 2 * t;
        float2 f0 = __half22float2(*reinterpret_cast<const __half2*>(&h[(size_t)r0 * DD + cb]));
        float2 f1 = __half22float2(*reinterpret_cast<const __half2*>(&h[(size_t)r1 * DD + cb]));
        float ga = gamma[cb], gb = gamma[cb + 1];
        float ba = beta[cb], bb = beta[cb + 1];
        float y0 = (acc[ni][0] + f0.x - mu0) * inv0 * ga + ba;
        float y1 = (acc[ni][1] + f0.y - mu0) * inv0 * gb + bb;
        float y2 = (acc[ni][2] + f1.x - mu1) * inv1 * ga + ba;
        float y3 = (acc[ni][3] + f1.y - mu1) * inv1 * gb + bb;
        *reinterpret_cast<__half2*>(&h[(size_t)r0 * DD + cb]) = __floats2half2_rn(y0, y1);
        *reinterpret_cast<__half2*>(&h[(size_t)r1 * DD + cb]) = __floats2half2_rn(y2, y3);
    }
}

// ---------------- fused prep ----------------
__device__ __forceinline__ void trans_block(const float* __restrict__ src,
                                            __half* __restrict__ dst,
                                            int R, int C, int bx, int by,
                                            int tx, int ty)
{
    __shared__ float t[32][33];
    int cb = bx * 32, rb = by * 32;
    #pragma unroll
    for (int j = 0; j < 4; j++)
        t[ty + j * 8][tx] = src[(size_t)(rb + ty + j * 8) * C + cb + tx];
    __syncthreads();
    #pragma unroll
    for (int j = 0; j < 4; j++)
        dst[(size_t)(cb + ty + j * 8) * R + rb + tx] = __float2half_rn(t[tx][ty + j * 8]);
}

__global__ __launch_bounds__(256) void prep_main(
    const float* __restrict__ h_in, __half* __restrict__ h16,
    const float* __restrict__ Wq, const float* __restrict__ Wk,
    const float* __restrict__ Wv, __half* __restrict__ wqkvT)
{
    int b = blockIdx.x;
    int tid = threadIdx.x;
    int tx = tid & 31, ty = tid >> 5;
    if (b < 64) {
        trans_block(Wq, wqkvT, DD, DD, b & 7, b >> 3, tx, ty);
    } else if (b < 128) {
        int bb = b - 64;
        trans_block(Wk, wqkvT + 256 * DD, DD, DD, bb & 7, bb >> 3, tx, ty);
    } else if (b < 192) {
        int bb = b - 128;
        trans_block(Wv, wqkvT + 512 * DD, DD, DD, bb & 7, bb >> 3, tx, ty);
    } else {
        int idx = (b - 192) * 2048 + tid * 8;
        float4 a = *reinterpret_cast<const float4*>(&h_in[idx]);
        float4 c = *reinterpret_cast<const float4*>(&h_in[idx + 4]);
        uint4 o;
        *reinterpret_cast<__half2*>(&o.x) = __floats2half2_rn(a.x, a.y);
        *reinterpret_cast<__half2*>(&o.y) = __floats2half2_rn(a.z, a.w);
        *reinterpret_cast<__half2*>(&o.z) = __floats2half2_rn(c.x, c.y);
        *reinterpret_cast<__half2*>(&o.w) = __floats2half2_rn(c.z, c.w);
        *reinterpret_cast<uint4*>(&h16[idx]) = o;
    }
}

__global__ __launch_bounds__(256) void prep_s2(
    const float* __restrict__ Wq, const float* __restrict__ Wk,
    const float* __restrict__ Wv, const float* __restrict__ Wo,
    const float* __restrict__ w1, const float* __restrict__ w2,
    __half* __restrict__ wqkvT, __half* __restrict__ woT,
    __half* __restrict__ w1T, __half* __restrict__ w2T)
{
    int b = blockIdx.x;
    int tid = threadIdx.x;
    int tx = tid & 31, ty = tid >> 5;
    const size_t WSZ = (size_t)DD * DD;
    __half* qkv1 = wqkvT + (size_t)QKVW * DD;
    if (b < 64) {
        trans_block(Wq + WSZ, qkv1, DD, DD, b & 7, b >> 3, tx, ty);
    } else if (b < 128) {
        int bb = b - 64;
        trans_block(Wk + WSZ, qkv1 + 256 * DD, DD, DD, bb & 7, bb >> 3, tx, ty);
    } else if (b < 192) {
        int bb = b - 128;
        trans_block(Wv + WSZ, qkv1 + 512 * DD, DD, DD, bb & 7, bb >> 3, tx, ty);
    } else if (b < 256) {
        int bb = b - 192;
        trans_block(Wo, woT, DD, DD, bb & 7, bb >> 3, tx, ty);
    } else if (b < 320) {
        int bb = b - 256;
        trans_block(Wo + WSZ, woT + WSZ, DD, DD, bb & 7, bb >> 3, tx, ty);
    } else if (b < 576) {
        int bb = b - 320;
        trans_block(w1, w1T, DD, HUSZ, bb & 31, bb >> 5, tx, ty);
    } else {
        int bb = b - 576;
        trans_block(w2, w2T, HUSZ, DD, bb & 7, bb >> 3, tx, ty);
    }
}

// ---------------- CSR build ----------------
__global__ void hist_dst(const int* __restrict__ dst, int* __restrict__ cnt)
{
    int i = blockIdx.x * blockDim.x + threadIdx.x;
    if (i < EE) atomicAdd(&cnt[dst[i]], 1);
}

__global__ __launch_bounds__(1024) void scan_offsets(const int* __restrict__ cnt,
                                                     int* __restrict__ off,
                                                     int* __restrict__ cur)
{
    __shared__ int wsum[32];
    __shared__ int carry_s;
    const int lane = threadIdx.x & 31;
    const int wid = threadIdx.x >> 5;
    if (threadIdx.x == 0) carry_s = 0;
    __syncthreads();
    for (int base = 0; base < NN; base += 1024) {
        int i = base + threadIdx.x;
        int v = (i < NN) ? cnt[i] : 0;
        int x = v;
        #pragma unroll
        for (int s = 1; s < 32; s <<= 1) {
            int t = __shfl_up_sync(0xffffffffu, x, s);
            if (lane >= s) x += t;
        }
        if (lane == 31) wsum[wid] = x;
        __syncthreads();
        if (wid == 0) {
            int w = wsum[lane];
            #pragma unroll
            for (int s = 1; s < 32; s <<= 1) {
                int t = __shfl_up_sync(0xffffffffu, w, s);
                if (lane >= s) w += t;
            }
            wsum[lane] = w;
        }
        __syncthreads();
        int warp_prefix = (wid > 0) ? wsum[wid - 1] : 0;
        int carry = carry_s;
        int excl = carry + warp_prefix + x - v;
        if (i < NN) { off[i] = excl; cur[i] = excl; }
        __syncthreads();
        if (threadIdx.x == 1023) carry_s = carry + wsum[31];
        __syncthreads();
    }
    if (threadIdx.x == 0) off[NN] = carry_s;
}

__global__ void scatter_csr(const int* __restrict__ src, const int* __restrict__ dst,
                            int* __restrict__ cur, int* __restrict__ csrc)
{
    int i = blockIdx.x * blockDim.x + threadIdx.x;
    if (i >= EE) return;
    int pos = atomicAdd(&cur[dst[i]], 1);
    csrc[pos] = src[i];
}

// ---------------- fused attention gather: one warp per dst node ----------------
__global__ __launch_bounds__(256) void attn_gather(
    const int* __restrict__ off, const int* __restrict__ csrc,
    const __half* __restrict__ qkv, __half* __restrict__ agg)
{
    int node = (blockIdx.x * blockDim.x + threadIdx.x) >> 5;
    int lane = threadIdx.x & 31;
    if (node >= NN) return;
    const int h = lane >> 2;
    const int sub = lane & 3;
    const int doff = h * 32 + sub * 8;

    int beg = off[node], end = off[node + 1];

    uint4 qb = *reinterpret_cast<const uint4*>(&qkv[(size_t)node * QKVW + doff]);
    float2 qf0 = __half22float2(*reinterpret_cast<__half2*>(&qb.x));
    float2 qf1 = __half22float2(*reinterpret_cast<__half2*>(&qb.y));
    float2 qf2 = __half22float2(*reinterpret_cast<__half2*>(&qb.z));
    float2 qf3 = __half22float2(*reinterpret_cast<__half2*>(&qb.w));

    const float scale = 0.17677669529663687f;

    float mA = -INFINITY, zA = 0.f;
    float mB = -INFINITY, zB = 0.f;
    float accA[8], accB[8];
    #pragma unroll
    for (int j = 0; j < 8; j++) { accA[j] = 0.f; accB[j] = 0.f; }

    int p = beg;
    for (; p + 1 < end; p += 2) {
        int sA = csrc[p];
        int sB = csrc[p + 1];
        const __half* bA = qkv + (size_t)sA * QKVW + 256 + doff;
        const __half* bB = qkv + (size_t)sB * QKVW + 256 + doff;
        uint4 krA = *reinterpret_cast<const uint4*>(bA);
        uint4 krB = *reinterpret_cast<const uint4*>(bB);
        uint4 vrA = *reinterpret_cast<const uint4*>(bA + 256);
        uint4 vrB = *reinterpret_cast<const uint4*>(bB + 256);

        float2 kA0 = __half22float2(*reinterpret_cast<__half2*>(&krA.x));
        float2 kA1 = __half22float2(*reinterpret_cast<__half2*>(&krA.y));
        float2 kA2 = __half22float2(*reinterpret_cast<__half2*>(&krA.z));
        float2 kA3 = __half22float2(*reinterpret_cast<__half2*>(&krA.w));
        float2 kB0 = __half22float2(*reinterpret_cast<__half2*>(&krB.x));
        float2 kB1 = __half22float2(*reinterpret_cast<__half2*>(&krB.y));
        float2 kB2 = __half22float2(*reinterpret_cast<__half2*>(&krB.z));
        float2 kB3 = __half22float2(*reinterpret_cast<__half2*>(&krB.w));

        float pA = qf0.x * kA0.x + qf0.y * kA0.y + qf1.x * kA1.x + qf1.y * kA1.y
                 + qf2.x * kA2.x + qf2.y * kA2.y + qf3.x * kA3.x + qf3.y * kA3.y;
        float pB = qf0.x * kB0.x + qf0.y * kB0.y + qf1.x * kB1.x + qf1.y * kB1.y
                 + qf2.x * kB2.x + qf2.y * kB2.y + qf3.x * kB3.x + qf3.y * kB3.y;
        pA += __shfl_xor_sync(0xffffffffu, pA, 1);
        pB += __shfl_xor_sync(0xffffffffu, pB, 1);
        pA += __shfl_xor_sync(0xffffffffu, pA, 2);
        pB += __shfl_xor_sync(0xffffffffu, pB, 2);

        float lA = pA * scale;
        float lB = pB * scale;

        float2 vA0 = __half22float2(*reinterpret_cast<__half2*>(&vrA.x));
        float2 vA1 = __half22float2(*reinterpret_cast<__half2*>(&vrA.y));
        float2 vA2 = __half22float2(*reinterpret_cast<__half2*>(&vrA.z));
        float2 vA3 = __half22float2(*reinterpret_cast<__half2*>(&vrA.w));
        float2 vB0 = __half22float2(*reinterpret_cast<__half2*>(&vrB.x));
        float2 vB1 = __half22float2(*reinterpret_cast<__half2*>(&vrB.y));
        float2 vB2 = __half22float2(*reinterpret_cast<__half2*>(&vrB.z));
        float2 vB3 = __half22float2(*reinterpret_cast<__half2*>(&vrB.w));

        float nmA = fmaxf(mA, lA);
        float fA = __expf(mA - nmA);
        float aA = __expf(lA - nmA);
        zA = zA * fA + aA;
        mA = nmA;
        accA[0] = accA[0] * fA + aA * vA0.x;
        accA[1] = accA[1] * fA + aA * vA0.y;
        accA[2] = accA[2] * fA + aA * vA1.x;
        accA[3] = accA[3] * fA + aA * vA1.y;
        accA[4] = accA[4] * fA + aA * vA2.x;
        accA[5] = accA[5] * fA + aA * vA2.y;
        accA[6] = accA[6] * fA + aA * vA3.x;
        accA[7] = accA[7] * fA + aA * vA3.y;

        float nmB = fmaxf(mB, lB);
        float fB = __expf(mB - nmB);
        float aB = __expf(lB - nmB);
        zB = zB * fB + aB;
        mB = nmB;
        accB[0] = accB[0] * fB + aB * vB0.x;
        accB[1] = accB[1] * fB + aB * vB0.y;
        accB[2] = accB[2] * fB + aB * vB1.x;
        accB[3] = accB[3] * fB + aB * vB1.y;
        accB[4] = accB[4] * fB + aB * vB2.x;
        accB[5] = accB[5] * fB + aB * vB2.y;
        accB[6] = accB[6] * fB + aB * vB3.x;
        accB[7] = accB[7] * fB + aB * vB3.y;
    }
    if (p < end) {
        int s = csrc[p];
        const __half* b = qkv + (size_t)s * QKVW + 256 + doff;
        uint4 kr = *reinterpret_cast<const uint4*>(b);
        uint4 vr = *reinterpret_cast<const uint4*>(b + 256);
        float2 k0 = __half22float2(*reinterpret_cast<__half2*>(&kr.x));
        float2 k1 = __half22float2(*reinterpret_cast<__half2*>(&kr.y));
        float2 k2 = __half22float2(*reinterpret_cast<__half2*>(&kr.z));
        float2 k3 = __half22float2(*reinterpret_cast<__half2*>(&kr.w));
        float part = qf0.x * k0.x + qf0.y * k0.y + qf1.x * k1.x + qf1.y * k1.y
                   + qf2.x * k2.x + qf2.y * k2.y + qf3.x * k3.x + qf3.y * k3.y;
        part += __shfl_xor_sync(0xffffffffu, part, 1);
        part += __shfl_xor_sync(0xffffffffu, part, 2);
        float logit = part * scale;
        float2 v0 = __half22float2(*reinterpret_cast<__half2*>(&vr.x));
        float2 v1 = __half22float2(*reinterpret_cast<__half2*>(&vr.y));
        float2 v2 = __half22float2(*reinterpret_cast<__half2*>(&vr.z));
        float2 v3 = __half22float2(*reinterpret_cast<__half2*>(&vr.w));
        float nm = fmaxf(mA, logit);
        float f = __expf(mA - nm);
        float a = __expf(logit - nm);
        zA = zA * f + a;
        mA = nm;
        accA[0] = accA[0] * f + a * v0.x;
        accA[1] = accA[1] * f + a * v0.y;
        accA[2] = accA[2] * f + a * v1.x;
        accA[3] = accA[3] * f + a * v1.y;
        accA[4] = accA[4] * f + a * v2.x;
        accA[5] = accA[5] * f + a * v2.y;
        accA[6] = accA[6] * f + a * v3.x;
        accA[7] = accA[7] * f + a * v3.y;
    }

    float m = fmaxf(mA, mB);
    float fA = (zA > 0.f) ? __expf(mA - m) : 0.f;
    float fB = (zB > 0.f) ? __expf(mB - m) : 0.f;
    float z = zA * fA + zB * fB;
    float inv = 1.f / (z + 1e-9f);

    uint4 outw;
    float o[8];
    #pragma unroll
    for (int j = 0; j < 8; j++) o[j] = (accA[j] * fA + accB[j] * fB) * inv;
    if (end == beg) {
        #pragma unroll
        for (int j = 0; j < 8; j++) o[j] = 0.f;
    }
    *reinterpret_cast<__half2*>(&outw.x) = __floats2half2_rn(o[0], o[1]);
    *reinterpret_cast<__half2*>(&outw.y) = __floats2half2_rn(o[2], o[3]);
    *reinterpret_cast<__half2*>(&outw.z) = __floats2half2_rn(o[4], o[5]);
    *reinterpret_cast<__half2*>(&outw.w) = __floats2half2_rn(o[6], o[7]);
    *reinterpret_cast<uint4*>(&agg[(size_t)node * DD + doff]) = outw;
}

// ---------------- launch ----------------
extern "C" void kernel_launch(void* const* d_in, const int* in_sizes, int n_in,
                              void* d_out, int out_size)
{
    const float* h_in = (const float*)d_in[0];
    const int* src = (const int*)d_in[1];
    const int* dst = (const int*)d_in[2];
    const float* Wq = (const float*)d_in[3];
    const float* Wk = (const float*)d_in[4];
    const float* Wv = (const float*)d_in[5];
    const float* Wo = (const float*)d_in[6];
    const float* ln_g = (const float*)d_in[7];
    const float* ln_b = (const float*)d_in[8];
    const float* w1 = (const float*)d_in[9];
    const float* b1 = (const float*)d_in[10];
    const float* w2 = (const float*)d_in[11];
    const float* b2 = (const float*)d_in[12];
    float* out = (float*)d_out;

    __half *ph16, *pqkv16, *pagg16, *pffn16, *pwqkvT, *pwoT, *pw1T, *pw2T;
    int *pcnt, *poff, *pcur, *pcsrc;
    cudaGetSymbolAddress((void**)&ph16, g_h16);
    cudaGetSymbolAddress((void**)&pqkv16, g_qkv16);
    cudaGetSymbolAddress((void**)&pagg16, g_agg16);
    cudaGetSymbolAddress((void**)&pffn16, g_ffn16);
    cudaGetSymbolAddress((void**)&pwqkvT, g_wqkvT);
    cudaGetSymbolAddress((void**)&pwoT, g_woT);
    cudaGetSymbolAddress((void**)&pw1T, g_w1T);
    cudaGetSymbolAddress((void**)&pw2T, g_w2T);
    cudaGetSymbolAddress((void**)&pcnt, g_cnt);
    cudaGetSymbolAddress((void**)&poff, g_off);
    cudaGetSymbolAddress((void**)&pcur, g_cur);
    cudaGetSymbolAddress((void**)&pcsrc, g_csrc);

    static cudaStream_t s2 = nullptr;
    static cudaEvent_t ev_fork = nullptr, ev_join = nullptr;
    static bool init_done = false;
    if (!init_done) {
        cudaFuncSetAttribute(gemm_h, cudaFuncAttributeMaxDynamicSharedMemorySize, GEMM_SMEM);
        cudaFuncSetAttribute(gemm_h64, cudaFuncAttributeMaxDynamicSharedMemorySize, GEMM64_SMEM);
        cudaFuncSetAttribute(gemm_ln, cudaFuncAttributeMaxDynamicSharedMemorySize, GEMMLN_SMEM);
        cudaStreamCreateWithFlags(&s2, cudaStreamNonBlocking);
        cudaEventCreateWithFlags(&ev_fork, cudaEventDisableTiming);
        cudaEventCreateWithFlags(&ev_join, cudaEventDisableTiming);
        init_done = true;
    }

    // fork: CSR build + remaining weight transposes on s2
    cudaEventRecord(ev_fork, 0);
    cudaStreamWaitEvent(s2, ev_fork, 0);

    prep_s2<<<832, 256, 0, s2>>>(Wq, Wk, Wv, Wo, w1, w2, pwqkvT, pwoT, pw1T, pw2T);
    cudaMemsetAsync(pcnt, 0, NN * sizeof(int), s2);
    hist_dst<<<(EE + 255) / 256, 256, 0, s2>>>(dst, pcnt);
    scan_offsets<<<1, 1024, 0, s2>>>(pcnt, poff, pcur);
    scatter_csr<<<(EE + 255) / 256, 256, 0, s2>>>(src, dst, pcur, pcsrc);
    cudaEventRecord(ev_join, s2);

    // main stream: fused h->fp16 + layer-0 qkv transposes
    prep_main<<<192 + 2500, 256>>>(h_in, ph16, Wq, Wk, Wv, pwqkvT);

    dim3 grid_qkv(QKVW / 128, (NN + 127) / 128);
    dim3 grid_d64(DD / 128, (NN + 63) / 64);
    dim3 grid_hus(HUSZ / 128, (NN + 127) / 128);

    for (int l = 0; l < LL; l++) {
        const __half* wqkvT = pwqkvT + (size_t)l * QKVW * DD;
        const __half* woT = pwoT + (size_t)l * DD * DD;
        const float* lg = ln_g + (size_t)l * DD;
        const float* lb = ln_b + (size_t)l * DD;

        gemm_h<<<grid_qkv, 256, GEMM_SMEM>>>(ph16, wqkvT, nullptr, nullptr, pqkv16,
                                             NN, QKVW, DD, 0);
        if (l == 0) cudaStreamWaitEvent(0, ev_join, 0);
        attn_gather<<<(NN * 32 + 255) / 256, 256>>>(poff, pcsrc, pqkv16, pagg16);
        gemm_ln<<<NN / 32, 256, GEMMLN_SMEM>>>(pagg16, woT, ph16, lg, lb);
    }

    gemm_h<<<grid_hus, 256, GEMM_SMEM>>>(ph16, pw1T, b1, nullptr, pffn16,
                                         NN, HUSZ, DD, 1);
    gemm_h64<<<grid_d64, 256, GEMM64_SMEM>>>(pffn16, pw2T, b2, out, nullptr,
                                             NN, DD, HUSZ, 0);
}

// round 16
// speedup vs baseline: 1.0561x; 1.0561x over previous
#include <cuda_runtime.h>
#include <cuda_fp16.h>
#include <math.h>
#include <stdint.h>

#define NN 20000
#define EE 320000
#define DD 256
#define HH 8
#define LL 2
#define HUSZ 1024
#define QKVW 768

// ---------------- scratch (no allocation allowed) ----------------
__device__ __half g_h16[NN * DD];
__device__ __half g_qkv16[NN * QKVW];
__device__ __half g_agg16[NN * DD];
__device__ __half g_attn16[NN * DD];
__device__ __half g_ffn16[NN * HUSZ];
__device__ __half g_wqkvT[LL * QKVW * DD];
__device__ __half g_woT[LL * DD * DD];
__device__ __half g_w1T[HUSZ * DD];
__device__ __half g_w2T[DD * HUSZ];
__device__ int    g_cnt[NN];
__device__ int    g_off[NN + 1];
__device__ int    g_cur[NN];
__device__ int    g_csrc[EE];

// ---------------- helpers ----------------
__device__ __forceinline__ void cp16h(__half* smem_ptr, const __half* gptr, bool p) {
    unsigned s = (unsigned)__cvta_generic_to_shared(smem_ptr);
    int bytes = p ? 16 : 0;
    asm volatile("cp.async.cg.shared.global [%0], [%1], 16, %2;\n"
                 :: "r"(s), "l"(gptr), "r"(bytes));
}
__device__ __forceinline__ void cp_commit() { asm volatile("cp.async.commit_group;\n" ::: "memory"); }
template <int N>
__device__ __forceinline__ void cp_wait() { asm volatile("cp.async.wait_group %0;\n" :: "n"(N) : "memory"); }

#define HSTRIDE 40
#define NSTAGE 3

// ================ gemm_h: BM=128, BN=128 ================
#define H_STAGE (128 * HSTRIDE)
#define GEMM_SMEM ((size_t)NSTAGE * 2 * H_STAGE * sizeof(__half))

__global__ __launch_bounds__(256) void gemm_h(
    const __half* __restrict__ A, const __half* __restrict__ BT,
    const float* __restrict__ bias, float* __restrict__ Cf, __half* __restrict__ Ch,
    int M, int Nc, int Kc, int relu)
{
    extern __shared__ __half smh[];

    const int tid = threadIdx.x;
    const int wid = tid >> 5;
    const int lane = tid & 31;
    const int g = lane >> 2;
    const int t = lane & 3;

    const int warp_m = wid >> 2;
    const int warp_n = wid & 3;
    const int row0 = blockIdx.y * 128;
    const int col0 = blockIdx.x * 128;

    const uint32_t sh0 = (uint32_t)__cvta_generic_to_shared(smh);

    const int a_lane = ((lane & 7) + ((lane >> 3) & 1) * 8) * HSTRIDE + (lane >> 4) * 8;
    const int b_lane4 = (lane & 7) * HSTRIDE + ((lane >> 3) & 1) * 8 + (lane >> 4) * 8 * HSTRIDE;

    float acc[4][4][4];
    #pragma unroll
    for (int mi = 0; mi < 4; mi++)
        #pragma unroll
        for (int ni = 0; ni < 4; ni++)
            #pragma unroll
            for (int r = 0; r < 4; r++) acc[mi][ni][r] = 0.f;

    const int ntiles = Kc >> 5;

    auto load_stage = [&](int st, int k0) {
        __half* as = smh + st * H_STAGE;
        __half* bs = smh + (NSTAGE + st) * H_STAGE;
        #pragma unroll
        for (int i = 0; i < 2; i++) {
            int lin = i * 256 + tid;
            int row = lin >> 2;
            int seg = (lin & 3) * 8;
            cp16h(&as[row * HSTRIDE + seg],
                  &A[(size_t)(row0 + row) * Kc + k0 + seg],
                  row0 + row < M);
            cp16h(&bs[row * HSTRIDE + seg],
                  &BT[(size_t)(col0 + row) * Kc + k0 + seg],
                  true);
        }
    };

    load_stage(0, 0);
    cp_commit();
    load_stage(1, 32);
    cp_commit();

    for (int kt = 0; kt < ntiles; kt++) {
        cp_wait<1>();
        __syncthreads();
        if (kt + 2 < ntiles) load_stage((kt + 2) % NSTAGE, (kt + 2) * 32);
        cp_commit();

        const int st = kt % NSTAGE;
        const uint32_t as_b = sh0 + (uint32_t)(st * H_STAGE) * 2;
        const uint32_t bs_b = sh0 + (uint32_t)((NSTAGE + st) * H_STAGE) * 2;

        #pragma unroll
        for (int ks = 0; ks < 2; ks++) {
            const int kk = ks * 16;
            const uint32_t a_base = as_b + 2u * (warp_m * 64 * HSTRIDE + kk + a_lane);
            const uint32_t b_base = bs_b + 2u * (warp_n * 32 * HSTRIDE + kk + b_lane4);

            unsigned af[4][4];
            #pragma unroll
            for (int mi = 0; mi < 4; mi++) {
                uint32_t addr = a_base + 2u * (mi * 16 * HSTRIDE);
                asm volatile("ldmatrix.sync.aligned.m8n8.x4.shared.b16 {%0,%1,%2,%3}, [%4];"
                             : "=r"(af[mi][0]), "=r"(af[mi][1]), "=r"(af[mi][2]), "=r"(af[mi][3])
                             : "r"(addr));
            }
            unsigned bf[4][2];
            #pragma unroll
            for (int np = 0; np < 2; np++) {
                uint32_t addr = b_base + 2u * (np * 16 * HSTRIDE);
                asm volatile("ldmatrix.sync.aligned.m8n8.x4.shared.b16 {%0,%1,%2,%3}, [%4];"
                             : "=r"(bf[2 * np][0]), "=r"(bf[2 * np][1]),
                               "=r"(bf[2 * np + 1][0]), "=r"(bf[2 * np + 1][1])
                             : "r"(addr));
            }
            #pragma unroll
            for (int mi = 0; mi < 4; mi++)
                #pragma unroll
                for (int ni = 0; ni < 4; ni++) {
                    asm volatile(
                        "mma.sync.aligned.m16n8k16.row.col.f32.f16.f16.f32 "
                        "{%0,%1,%2,%3}, {%4,%5,%6,%7}, {%8,%9}, {%0,%1,%2,%3};"
                        : "+f"(acc[mi][ni][0]), "+f"(acc[mi][ni][1]),
                          "+f"(acc[mi][ni][2]), "+f"(acc[mi][ni][3])
                        : "r"(af[mi][0]), "r"(af[mi][1]), "r"(af[mi][2]), "r"(af[mi][3]),
                          "r"(bf[ni][0]), "r"(bf[ni][1]));
                }
        }
    }

    #pragma unroll
    for (int mi = 0; mi < 4; mi++) {
        int rb = row0 + warp_m * 64 + mi * 16 + g;
        #pragma unroll
        for (int ni = 0; ni < 4; ni++) {
            int cb = col0 + warp_n * 32 + ni * 8 + 2 * t;
            #pragma unroll
            for (int half = 0; half < 2; half++) {
                int r = rb + half * 8;
                if (r >= M) continue;
                float v0 = acc[mi][ni][half * 2 + 0];
                float v1 = acc[mi][ni][half * 2 + 1];
                if (bias) { v0 += bias[cb]; v1 += bias[cb + 1]; }
                if (relu) { v0 = fmaxf(v0, 0.f); v1 = fmaxf(v1, 0.f); }
                if (Ch) {
                    *reinterpret_cast<__half2*>(&Ch[(size_t)r * Nc + cb]) =
                        __floats2half2_rn(v0, v1);
                } else {
                    *reinterpret_cast<float2*>(&Cf[(size_t)r * Nc + cb]) =
                        make_float2(v0, v1);
                }
            }
        }
    }
}

// ================ gemm_h64: BM=64, BN=128 ================
#define A64_STAGE (64 * HSTRIDE)
#define B64_STAGE (128 * HSTRIDE)
#define GEMM64_SMEM ((size_t)NSTAGE * (A64_STAGE + B64_STAGE) * sizeof(__half))

__global__ __launch_bounds__(256) void gemm_h64(
    const __half* __restrict__ A, const __half* __restrict__ BT,
    const float* __restrict__ bias, float* __restrict__ Cf, __half* __restrict__ Ch,
    int M, int Nc, int Kc, int relu)
{
    extern __shared__ __half smh[];

    const int tid = threadIdx.x;
    const int wid = tid >> 5;
    const int lane = tid & 31;
    const int g = lane >> 2;
    const int t = lane & 3;

    const int warp_m = wid >> 2;
    const int warp_n = wid & 3;
    const int row0 = blockIdx.y * 64;
    const int col0 = blockIdx.x * 128;

    const uint32_t sh0 = (uint32_t)__cvta_generic_to_shared(smh);

    const int a_lane = ((lane & 7) + ((lane >> 3) & 1) * 8) * HSTRIDE + (lane >> 4) * 8;
    const int b_lane4 = (lane & 7) * HSTRIDE + ((lane >> 3) & 1) * 8 + (lane >> 4) * 8 * HSTRIDE;

    float acc[2][4][4];
    #pragma unroll
    for (int mi = 0; mi < 2; mi++)
        #pragma unroll
        for (int ni = 0; ni < 4; ni++)
            #pragma unroll
            for (int r = 0; r < 4; r++) acc[mi][ni][r] = 0.f;

    const int ntiles = Kc >> 5;

    auto load_stage = [&](int st, int k0) {
        __half* as = smh + st * A64_STAGE;
        __half* bs = smh + NSTAGE * A64_STAGE + st * B64_STAGE;
        {
            int row = tid >> 2;
            int seg = (tid & 3) * 8;
            cp16h(&as[row * HSTRIDE + seg],
                  &A[(size_t)(row0 + row) * Kc + k0 + seg],
                  row0 + row < M);
        }
        #pragma unroll
        for (int i = 0; i < 2; i++) {
            int lin = i * 256 + tid;
            int row = lin >> 2;
            int seg = (lin & 3) * 8;
            cp16h(&bs[row * HSTRIDE + seg],
                  &BT[(size_t)(col0 + row) * Kc + k0 + seg],
                  true);
        }
    };

    load_stage(0, 0);
    cp_commit();
    load_stage(1, 32);
    cp_commit();

    for (int kt = 0; kt < ntiles; kt++) {
        cp_wait<1>();
        __syncthreads();
        if (kt + 2 < ntiles) load_stage((kt + 2) % NSTAGE, (kt + 2) * 32);
        cp_commit();

        const int st = kt % NSTAGE;
        const uint32_t as_b = sh0 + (uint32_t)(st * A64_STAGE) * 2;
        const uint32_t bs_b = sh0 + (uint32_t)(NSTAGE * A64_STAGE + st * B64_STAGE) * 2;

        #pragma unroll
        for (int ks = 0; ks < 2; ks++) {
            const int kk = ks * 16;
            const uint32_t a_base = as_b + 2u * (warp_m * 32 * HSTRIDE + kk + a_lane);
            const uint32_t b_base = bs_b + 2u * (warp_n * 32 * HSTRIDE + kk + b_lane4);

            unsigned af[2][4];
            #pragma unroll
            for (int mi = 0; mi < 2; mi++) {
                uint32_t addr = a_base + 2u * (mi * 16 * HSTRIDE);
                asm volatile("ldmatrix.sync.aligned.m8n8.x4.shared.b16 {%0,%1,%2,%3}, [%4];"
                             : "=r"(af[mi][0]), "=r"(af[mi][1]), "=r"(af[mi][2]), "=r"(af[mi][3])
                             : "r"(addr));
            }
            unsigned bf[4][2];
            #pragma unroll
            for (int np = 0; np < 2; np++) {
                uint32_t addr = b_base + 2u * (np * 16 * HSTRIDE);
                asm volatile("ldmatrix.sync.aligned.m8n8.x4.shared.b16 {%0,%1,%2,%3}, [%4];"
                             : "=r"(bf[2 * np][0]), "=r"(bf[2 * np][1]),
                               "=r"(bf[2 * np + 1][0]), "=r"(bf[2 * np + 1][1])
                             : "r"(addr));
            }
            #pragma unroll
            for (int mi = 0; mi < 2; mi++)
                #pragma unroll
                for (int ni = 0; ni < 4; ni++) {
                    asm volatile(
                        "mma.sync.aligned.m16n8k16.row.col.f32.f16.f16.f32 "
                        "{%0,%1,%2,%3}, {%4,%5,%6,%7}, {%8,%9}, {%0,%1,%2,%3};"
                        : "+f"(acc[mi][ni][0]), "+f"(acc[mi][ni][1]),
                          "+f"(acc[mi][ni][2]), "+f"(acc[mi][ni][3])
                        : "r"(af[mi][0]), "r"(af[mi][1]), "r"(af[mi][2]), "r"(af[mi][3]),
                          "r"(bf[ni][0]), "r"(bf[ni][1]));
                }
        }
    }

    #pragma unroll
    for (int mi = 0; mi < 2; mi++) {
        int rb = row0 + warp_m * 32 + mi * 16 + g;
        #pragma unroll
        for (int ni = 0; ni < 4; ni++) {
            int cb = col0 + warp_n * 32 + ni * 8 + 2 * t;
            #pragma unroll
            for (int half = 0; half < 2; half++) {
                int r = rb + half * 8;
                if (r >= M) continue;
                float v0 = acc[mi][ni][half * 2 + 0];
                float v1 = acc[mi][ni][half * 2 + 1];
                if (bias) { v0 += bias[cb]; v1 += bias[cb + 1]; }
                if (relu) { v0 = fmaxf(v0, 0.f); v1 = fmaxf(v1, 0.f); }
                if (Ch) {
                    *reinterpret_cast<__half2*>(&Ch[(size_t)r * Nc + cb]) =
                        __floats2half2_rn(v0, v1);
                } else {
                    *reinterpret_cast<float2*>(&Cf[(size_t)r * Nc + cb]) =
                        make_float2(v0, v1);
                }
            }
        }
    }
}

// ---------------- fused prep ----------------
__device__ __forceinline__ void trans_block(const float* __restrict__ src,
                                            __half* __restrict__ dst,
                                            int R, int C, int bx, int by,
                                            int tx, int ty)
{
    __shared__ float t[32][33];
    int cb = bx * 32, rb = by * 32;
    #pragma unroll
    for (int j = 0; j < 4; j++)
        t[ty + j * 8][tx] = src[(size_t)(rb + ty + j * 8) * C + cb + tx];
    __syncthreads();
    #pragma unroll
    for (int j = 0; j < 4; j++)
        dst[(size_t)(cb + ty + j * 8) * R + rb + tx] = __float2half_rn(t[tx][ty + j * 8]);
}

__global__ __launch_bounds__(256) void prep_main(
    const float* __restrict__ h_in, __half* __restrict__ h16,
    const float* __restrict__ Wq, const float* __restrict__ Wk,
    const float* __restrict__ Wv, __half* __restrict__ wqkvT)
{
    int b = blockIdx.x;
    int tid = threadIdx.x;
    int tx = tid & 31, ty = tid >> 5;
    if (b < 64) {
        trans_block(Wq, wqkvT, DD, DD, b & 7, b >> 3, tx, ty);
    } else if (b < 128) {
        int bb = b - 64;
        trans_block(Wk, wqkvT + 256 * DD, DD, DD, bb & 7, bb >> 3, tx, ty);
    } else if (b < 192) {
        int bb = b - 128;
        trans_block(Wv, wqkvT + 512 * DD, DD, DD, bb & 7, bb >> 3, tx, ty);
    } else {
        int idx = (b - 192) * 2048 + tid * 8;
        float4 a = *reinterpret_cast<const float4*>(&h_in[idx]);
        float4 c = *reinterpret_cast<const float4*>(&h_in[idx + 4]);
        uint4 o;
        *reinterpret_cast<__half2*>(&o.x) = __floats2half2_rn(a.x, a.y);
        *reinterpret_cast<__half2*>(&o.y) = __floats2half2_rn(a.z, a.w);
        *reinterpret_cast<__half2*>(&o.z) = __floats2half2_rn(c.x, c.y);
        *reinterpret_cast<__half2*>(&o.w) = __floats2half2_rn(c.z, c.w);
        *reinterpret_cast<uint4*>(&h16[idx]) = o;
    }
}

__global__ __launch_bounds__(256) void prep_s2(
    const float* __restrict__ Wq, const float* __restrict__ Wk,
    const float* __restrict__ Wv, const float* __restrict__ Wo,
    const float* __restrict__ w1, const float* __restrict__ w2,
    __half* __restrict__ wqkvT, __half* __restrict__ woT,
    __half* __restrict__ w1T, __half* __restrict__ w2T)
{
    int b = blockIdx.x;
    int tid = threadIdx.x;
    int tx = tid & 31, ty = tid >> 5;
    const size_t WSZ = (size_t)DD * DD;
    __half* qkv1 = wqkvT + (size_t)QKVW * DD;
    if (b < 64) {
        trans_block(Wq + WSZ, qkv1, DD, DD, b & 7, b >> 3, tx, ty);
    } else if (b < 128) {
        int bb = b - 64;
        trans_block(Wk + WSZ, qkv1 + 256 * DD, DD, DD, bb & 7, bb >> 3, tx, ty);
    } else if (b < 192) {
        int bb = b - 128;
        trans_block(Wv + WSZ, qkv1 + 512 * DD, DD, DD, bb & 7, bb >> 3, tx, ty);
    } else if (b < 256) {
        int bb = b - 192;
        trans_block(Wo, woT, DD, DD, bb & 7, bb >> 3, tx, ty);
    } else if (b < 320) {
        int bb = b - 256;
        trans_block(Wo + WSZ, woT + WSZ, DD, DD, bb & 7, bb >> 3, tx, ty);
    } else if (b < 576) {
        int bb = b - 320;
        trans_block(w1, w1T, DD, HUSZ, bb & 31, bb >> 5, tx, ty);
    } else {
        int bb = b - 576;
        trans_block(w2, w2T, HUSZ, DD, bb & 7, bb >> 3, tx, ty);
    }
}

// ---------------- CSR build ----------------
__global__ void hist_dst(const int* __restrict__ dst, int* __restrict__ cnt)
{
    int i = blockIdx.x * blockDim.x + threadIdx.x;
    if (i < EE) atomicAdd(&cnt[dst[i]], 1);
}

__global__ __launch_bounds__(1024) void scan_offsets(const int* __restrict__ cnt,
                                                     int* __restrict__ off,
                                                     int* __restrict__ cur)
{
    __shared__ int wsum[32];
    __shared__ int carry_s;
    const int lane = threadIdx.x & 31;
    const int wid = threadIdx.x >> 5;
    if (threadIdx.x == 0) carry_s = 0;
    __syncthreads();
    for (int base = 0; base < NN; base += 1024) {
        int i = base + threadIdx.x;
        int v = (i < NN) ? cnt[i] : 0;
        int x = v;
        #pragma unroll
        for (int s = 1; s < 32; s <<= 1) {
            int t = __shfl_up_sync(0xffffffffu, x, s);
            if (lane >= s) x += t;
        }
        if (lane == 31) wsum[wid] = x;
        __syncthreads();
        if (wid == 0) {
            int w = wsum[lane];
            #pragma unroll
            for (int s = 1; s < 32; s <<= 1) {
                int t = __shfl_up_sync(0xffffffffu, w, s);
                if (lane >= s) w += t;
            }
            wsum[lane] = w;
        }
        __syncthreads();
        int warp_prefix = (wid > 0) ? wsum[wid - 1] : 0;
        int carry = carry_s;
        int excl = carry + warp_prefix + x - v;
        if (i < NN) { off[i] = excl; cur[i] = excl; }
        __syncthreads();
        if (threadIdx.x == 1023) carry_s = carry + wsum[31];
        __syncthreads();
    }
    if (threadIdx.x == 0) off[NN] = carry_s;
}

__global__ void scatter_csr(const int* __restrict__ src, const int* __restrict__ dst,
                            int* __restrict__ cur, int* __restrict__ csrc)
{
    int i = blockIdx.x * blockDim.x + threadIdx.x;
    if (i >= EE) return;
    int pos = atomicAdd(&cur[dst[i]], 1);
    csrc[pos] = src[i];
}

// ---------------- fused attention gather: one warp per dst node ----------------
__global__ __launch_bounds__(256) void attn_gather(
    const int* __restrict__ off, const int* __restrict__ csrc,
    const __half* __restrict__ qkv, __half* __restrict__ agg)
{
    int node = (blockIdx.x * blockDim.x + threadIdx.x) >> 5;
    int lane = threadIdx.x & 31;
    if (node >= NN) return;
    const int h = lane >> 2;
    const int sub = lane & 3;
    const int doff = h * 32 + sub * 8;

    int beg = off[node], end = off[node + 1];

    uint4 qb = *reinterpret_cast<const uint4*>(&qkv[(size_t)node * QKVW + doff]);
    float2 qf0 = __half22float2(*reinterpret_cast<__half2*>(&qb.x));
    float2 qf1 = __half22float2(*reinterpret_cast<__half2*>(&qb.y));
    float2 qf2 = __half22float2(*reinterpret_cast<__half2*>(&qb.z));
    float2 qf3 = __half22float2(*reinterpret_cast<__half2*>(&qb.w));

    const float scale = 0.17677669529663687f;

    float mA = -INFINITY, zA = 0.f;
    float mB = -INFINITY, zB = 0.f;
    float accA[8], accB[8];
    #pragma unroll
    for (int j = 0; j < 8; j++) { accA[j] = 0.f; accB[j] = 0.f; }

    int p = beg;
    for (; p + 1 < end; p += 2) {
        int sA = csrc[p];
        int sB = csrc[p + 1];
        const __half* bA = qkv + (size_t)sA * QKVW + 256 + doff;
        const __half* bB = qkv + (size_t)sB * QKVW + 256 + doff;
        uint4 krA = *reinterpret_cast<const uint4*>(bA);
        uint4 krB = *reinterpret_cast<const uint4*>(bB);
        uint4 vrA = *reinterpret_cast<const uint4*>(bA + 256);
        uint4 vrB = *reinterpret_cast<const uint4*>(bB + 256);

        float2 kA0 = __half22float2(*reinterpret_cast<__half2*>(&krA.x));
        float2 kA1 = __half22float2(*reinterpret_cast<__half2*>(&krA.y));
        float2 kA2 = __half22float2(*reinterpret_cast<__half2*>(&krA.z));
        float2 kA3 = __half22float2(*reinterpret_cast<__half2*>(&krA.w));
        float2 kB0 = __half22float2(*reinterpret_cast<__half2*>(&krB.x));
        float2 kB1 = __half22float2(*reinterpret_cast<__half2*>(&krB.y));
        float2 kB2 = __half22float2(*reinterpret_cast<__half2*>(&krB.z));
        float2 kB3 = __half22float2(*reinterpret_cast<__half2*>(&krB.w));

        float pA = qf0.x * kA0.x + qf0.y * kA0.y + qf1.x * kA1.x + qf1.y * kA1.y
                 + qf2.x * kA2.x + qf2.y * kA2.y + qf3.x * kA3.x + qf3.y * kA3.y;
        float pB = qf0.x * kB0.x + qf0.y * kB0.y + qf1.x * kB1.x + qf1.y * kB1.y
                 + qf2.x * kB2.x + qf2.y * kB2.y + qf3.x * kB3.x + qf3.y * kB3.y;
        pA += __shfl_xor_sync(0xffffffffu, pA, 1);
        pB += __shfl_xor_sync(0xffffffffu, pB, 1);
        pA += __shfl_xor_sync(0xffffffffu, pA, 2);
        pB += __shfl_xor_sync(0xffffffffu, pB, 2);

        float lA = pA * scale;
        float lB = pB * scale;

        float2 vA0 = __half22float2(*reinterpret_cast<__half2*>(&vrA.x));
        float2 vA1 = __half22float2(*reinterpret_cast<__half2*>(&vrA.y));
        float2 vA2 = __half22float2(*reinterpret_cast<__half2*>(&vrA.z));
        float2 vA3 = __half22float2(*reinterpret_cast<__half2*>(&vrA.w));
        float2 vB0 = __half22float2(*reinterpret_cast<__half2*>(&vrB.x));
        float2 vB1 = __half22float2(*reinterpret_cast<__half2*>(&vrB.y));
        float2 vB2 = __half22float2(*reinterpret_cast<__half2*>(&vrB.z));
        float2 vB3 = __half22float2(*reinterpret_cast<__half2*>(&vrB.w));

        float nmA = fmaxf(mA, lA);
        float fA = __expf(mA - nmA);
        float aA = __expf(lA - nmA);
        zA = zA * fA + aA;
        mA = nmA;
        accA[0] = accA[0] * fA + aA * vA0.x;
        accA[1] = accA[1] * fA + aA * vA0.y;
        accA[2] = accA[2] * fA + aA * vA1.x;
        accA[3] = accA[3] * fA + aA * vA1.y;
        accA[4] = accA[4] * fA + aA * vA2.x;
        accA[5] = accA[5] * fA + aA * vA2.y;
        accA[6] = accA[6] * fA + aA * vA3.x;
        accA[7] = accA[7] * fA + aA * vA3.y;

        float nmB = fmaxf(mB, lB);
        float fB = __expf(mB - nmB);
        float aB = __expf(lB - nmB);
        zB = zB * fB + aB;
        mB = nmB;
        accB[0] = accB[0] * fB + aB * vB0.x;
        accB[1] = accB[1] * fB + aB * vB0.y;
        accB[2] = accB[2] * fB + aB * vB1.x;
        accB[3] = accB[3] * fB + aB * vB1.y;
        accB[4] = accB[4] * fB + aB * vB2.x;
        accB[5] = accB[5] * fB + aB * vB2.y;
        accB[6] = accB[6] * fB + aB * vB3.x;
        accB[7] = accB[7] * fB + aB * vB3.y;
    }
    if (p < end) {
        int s = csrc[p];
        const __half* b = qkv + (size_t)s * QKVW + 256 + doff;
        uint4 kr = *reinterpret_cast<const uint4*>(b);
        uint4 vr = *reinterpret_cast<const uint4*>(b + 256);
        float2 k0 = __half22float2(*reinterpret_cast<__half2*>(&kr.x));
        float2 k1 = __half22float2(*reinterpret_cast<__half2*>(&kr.y));
        float2 k2 = __half22float2(*reinterpret_cast<__half2*>(&kr.z));
        float2 k3 = __half22float2(*reinterpret_cast<__half2*>(&kr.w));
        float part = qf0.x * k0.x + qf0.y * k0.y + qf1.x * k1.x + qf1.y * k1.y
                   + qf2.x * k2.x + qf2.y * k2.y + qf3.x * k3.x + qf3.y * k3.y;
        part += __shfl_xor_sync(0xffffffffu, part, 1);
        part += __shfl_xor_sync(0xffffffffu, part, 2);
        float logit = part * scale;
        float2 v0 = __half22float2(*reinterpret_cast<__half2*>(&vr.x));
        float2 v1 = __half22float2(*reinterpret_cast<__half2*>(&vr.y));
        float2 v2 = __half22float2(*reinterpret_cast<__half2*>(&vr.z));
        float2 v3 = __half22float2(*reinterpret_cast<__half2*>(&vr.w));
        float nm = fmaxf(mA, logit);
        float f = __expf(mA - nm);
        float a = __expf(logit - nm);
        zA = zA * f + a;
        mA = nm;
        accA[0] = accA[0] * f + a * v0.x;
        accA[1] = accA[1] * f + a * v0.y;
        accA[2] = accA[2] * f + a * v1.x;
        accA[3] = accA[3] * f + a * v1.y;
        accA[4] = accA[4] * f + a * v2.x;
        accA[5] = accA[5] * f + a * v2.y;
        accA[6] = accA[6] * f + a * v3.x;
        accA[7] = accA[7] * f + a * v3.y;
    }

    float m = fmaxf(mA, mB);
    float fA = (zA > 0.f) ? __expf(mA - m) : 0.f;
    float fB = (zB > 0.f) ? __expf(mB - m) : 0.f;
    float z = zA * fA + zB * fB;
    float inv = 1.f / (z + 1e-9f);

    uint4 outw;
    float o[8];
    #pragma unroll
    for (int j = 0; j < 8; j++) o[j] = (accA[j] * fA + accB[j] * fB) * inv;
    if (end == beg) {
        #pragma unroll
        for (int j = 0; j < 8; j++) o[j] = 0.f;
    }
    *reinterpret_cast<__half2*>(&outw.x) = __floats2half2_rn(o[0], o[1]);
    *reinterpret_cast<__half2*>(&outw.y) = __floats2half2_rn(o[2], o[3]);
    *reinterpret_cast<__half2*>(&outw.z) = __floats2half2_rn(o[4], o[5]);
    *reinterpret_cast<__half2*>(&outw.w) = __floats2half2_rn(o[6], o[7]);
    *reinterpret_cast<uint4*>(&agg[(size_t)node * DD + doff]) = outw;
}

// ---------------- residual + layernorm: vectorized (uint4), fp32 math -------
// lane L owns cols [L*8, L*8+8); one warp per row.
__global__ void ln_residual(const __half* __restrict__ attn, __half* __restrict__ h,
                            const float* __restrict__ gamma, const float* __restrict__ beta)
{
    int row = (blockIdx.x * blockDim.x + threadIdx.x) >> 5;
    int lane = threadIdx.x & 31;
    if (row >= NN) return;
    const size_t base = (size_t)row * DD + lane * 8;

    uint4 aw = *reinterpret_cast<const uint4*>(&attn[base]);
    uint4 hw = *reinterpret_cast<const uint4*>(&h[base]);

    float x[8];
    {
        float2 a0 = __half22float2(*reinterpret_cast<__half2*>(&aw.x));
        float2 a1 = __half22float2(*reinterpret_cast<__half2*>(&aw.y));
        float2 a2 = __half22float2(*reinterpret_cast<__half2*>(&aw.z));
        float2 a3 = __half22float2(*reinterpret_cast<__half2*>(&aw.w));
        float2 h0 = __half22float2(*reinterpret_cast<__half2*>(&hw.x));
        float2 h1 = __half22float2(*reinterpret_cast<__half2*>(&hw.y));
        float2 h2 = __half22float2(*reinterpret_cast<__half2*>(&hw.z));
        float2 h3 = __half22float2(*reinterpret_cast<__half2*>(&hw.w));
        x[0] = a0.x + h0.x; x[1] = a0.y + h0.y;
        x[2] = a1.x + h1.x; x[3] = a1.y + h1.y;
        x[4] = a2.x + h2.x; x[5] = a2.y + h2.y;
        x[6] = a3.x + h3.x; x[7] = a3.y + h3.y;
    }

    float s = 0.f, q = 0.f;
    #pragma unroll
    for (int j = 0; j < 8; j++) { s += x[j]; q += x[j] * x[j]; }
    #pragma unroll
    for (int off = 16; off; off >>= 1) {
        s += __shfl_xor_sync(0xffffffffu, s, off);
        q += __shfl_xor_sync(0xffffffffu, q, off);
    }
    float mu = s * (1.f / DD);
    float inv = rsqrtf(fmaxf(q * (1.f / DD) - mu * mu, 0.f) + 1e-5f);

    float4 g0 = *reinterpret_cast<const float4*>(&gamma[lane * 8]);
    float4 g1 = *reinterpret_cast<const float4*>(&gamma[lane * 8 + 4]);
    float4 b0 = *reinterpret_cast<const float4*>(&beta[lane * 8]);
    float4 b1 = *reinterpret_cast<const float4*>(&beta[lane * 8 + 4]);

    uint4 ow;
    *reinterpret_cast<__half2*>(&ow.x) = __floats2half2_rn(
        (x[0] - mu) * inv * g0.x + b0.x, (x[1] - mu) * inv * g0.y + b0.y);
    *reinterpret_cast<__half2*>(&ow.y) = __floats2half2_rn(
        (x[2] - mu) * inv * g0.z + b0.z, (x[3] - mu) * inv * g0.w + b0.w);
    *reinterpret_cast<__half2*>(&ow.z) = __floats2half2_rn(
        (x[4] - mu) * inv * g1.x + b1.x, (x[5] - mu) * inv * g1.y + b1.y);
    *reinterpret_cast<__half2*>(&ow.w) = __floats2half2_rn(
        (x[6] - mu) * inv * g1.z + b1.z, (x[7] - mu) * inv * g1.w + b1.w);
    *reinterpret_cast<uint4*>(&h[base]) = ow;
}

// ---------------- launch ----------------
extern "C" void kernel_launch(void* const* d_in, const int* in_sizes, int n_in,
                              void* d_out, int out_size)
{
    const float* h_in = (const float*)d_in[0];
    const int* src = (const int*)d_in[1];
    const int* dst = (const int*)d_in[2];
    const float* Wq = (const float*)d_in[3];
    const float* Wk = (const float*)d_in[4];
    const float* Wv = (const float*)d_in[5];
    const float* Wo = (const float*)d_in[6];
    const float* ln_g = (const float*)d_in[7];
    const float* ln_b = (const float*)d_in[8];
    const float* w1 = (const float*)d_in[9];
    const float* b1 = (const float*)d_in[10];
    const float* w2 = (const float*)d_in[11];
    const float* b2 = (const float*)d_in[12];
    float* out = (float*)d_out;

    __half *ph16, *pqkv16, *pagg16, *pattn16, *pffn16, *pwqkvT, *pwoT, *pw1T, *pw2T;
    int *pcnt, *poff, *pcur, *pcsrc;
    cudaGetSymbolAddress((void**)&ph16, g_h16);
    cudaGetSymbolAddress((void**)&pqkv16, g_qkv16);
    cudaGetSymbolAddress((void**)&pagg16, g_agg16);
    cudaGetSymbolAddress((void**)&pattn16, g_attn16);
    cudaGetSymbolAddress((void**)&pffn16, g_ffn16);
    cudaGetSymbolAddress((void**)&pwqkvT, g_wqkvT);
    cudaGetSymbolAddress((void**)&pwoT, g_woT);
    cudaGetSymbolAddress((void**)&pw1T, g_w1T);
    cudaGetSymbolAddress((void**)&pw2T, g_w2T);
    cudaGetSymbolAddress((void**)&pcnt, g_cnt);
    cudaGetSymbolAddress((void**)&poff, g_off);
    cudaGetSymbolAddress((void**)&pcur, g_cur);
    cudaGetSymbolAddress((void**)&pcsrc, g_csrc);

    static cudaStream_t s2 = nullptr;
    static cudaEvent_t ev_fork = nullptr, ev_join = nullptr;
    static bool init_done = false;
    if (!init_done) {
        cudaFuncSetAttribute(gemm_h, cudaFuncAttributeMaxDynamicSharedMemorySize, GEMM_SMEM);
        cudaFuncSetAttribute(gemm_h64, cudaFuncAttributeMaxDynamicSharedMemorySize, GEMM64_SMEM);
        cudaStreamCreateWithFlags(&s2, cudaStreamNonBlocking);
        cudaEventCreateWithFlags(&ev_fork, cudaEventDisableTiming);
        cudaEventCreateWithFlags(&ev_join, cudaEventDisableTiming);
        init_done = true;
    }

    // fork: CSR build + remaining weight transposes on s2
    cudaEventRecord(ev_fork, 0);
    cudaStreamWaitEvent(s2, ev_fork, 0);

    prep_s2<<<832, 256, 0, s2>>>(Wq, Wk, Wv, Wo, w1, w2, pwqkvT, pwoT, pw1T, pw2T);
    cudaMemsetAsync(pcnt, 0, NN * sizeof(int), s2);
    hist_dst<<<(EE + 255) / 256, 256, 0, s2>>>(dst, pcnt);
    scan_offsets<<<1, 1024, 0, s2>>>(pcnt, poff, pcur);
    scatter_csr<<<(EE + 255) / 256, 256, 0, s2>>>(src, dst, pcur, pcsrc);
    cudaEventRecord(ev_join, s2);

    // main stream: fused h->fp16 + layer-0 qkv transposes
    prep_main<<<192 + 2500, 256>>>(h_in, ph16, Wq, Wk, Wv, pwqkvT);

    dim3 grid_qkv(QKVW / 128, (NN + 127) / 128);
    dim3 grid_d64(DD / 128, (NN + 63) / 64);
    dim3 grid_hus(HUSZ / 128, (NN + 127) / 128);

    for (int l = 0; l < LL; l++) {
        const __half* wqkvT = pwqkvT + (size_t)l * QKVW * DD;
        const __half* woT = pwoT + (size_t)l * DD * DD;
        const float* lg = ln_g + (size_t)l * DD;
        const float* lb = ln_b + (size_t)l * DD;

        gemm_h<<<grid_qkv, 256, GEMM_SMEM>>>(ph16, wqkvT, nullptr, nullptr, pqkv16,
                                             NN, QKVW, DD, 0);
        if (l == 0) cudaStreamWaitEvent(0, ev_join, 0);
        attn_gather<<<(NN * 32 + 255) / 256, 256>>>(poff, pcsrc, pqkv16, pagg16);
        gemm_h64<<<grid_d64, 256, GEMM64_SMEM>>>(pagg16, woT, nullptr, nullptr, pattn16,
                                                 NN, DD, DD, 0);
        ln_residual<<<(NN * 32 + 255) / 256, 256>>>(pattn16, ph16, lg, lb);
    }

    gemm_h<<<grid_hus, 256, GEMM_SMEM>>>(ph16, pw1T, b1, nullptr, pffn16,
                                         NN, HUSZ, DD, 1);
    gemm_h64<<<grid_d64, 256, GEMM64_SMEM>>>(pffn16, pw2T, b2, out, nullptr,
                                             NN, DD, HUSZ, 0);
}